// round 3
// baseline (speedup 1.0000x reference)
#include <cuda_runtime.h>
#include <cstdint>

// Problem constants
#define TT 128
#define SS 512
#define BB 512
#define GRID_F 148          // one CTA per SM, single wave
#define ENG 3               // 128-thread engines per CTA
#define NENG (GRID_F*ENG)   // 444 engines

__device__ float g_num[BB];
__device__ float g_denom[BB];

__device__ __forceinline__ float fex2(float x){ float r; asm("ex2.approx.f32 %0,%1;":"=f"(r):"f"(x)); return r; }
__device__ __forceinline__ float flg2(float x){ float r; asm("lg2.approx.f32 %0,%1;":"=f"(r):"f"(x)); return r; }

#define FMA2(d,a,b,c) asm("fma.rn.f32x2 %0,%1,%2,%3;":"=l"(d):"l"(a),"l"(b),"l"(c))
#define ADD2(d,a,b)   asm("add.rn.f32x2 %0,%1,%2;":"=l"(d):"l"(a),"l"(b))

#define L2E 1.4426950408889634f
#define LN2 0.6931471805599453f

// ---------------------------------------------------------------------------
// Forward algorithm (denominator). One 128-thread engine per batch sequence.
// Thread j owns column E[:,j] = exp(trans[:,j]) in 128 registers (64 f32x2).
// Per step: p_i = exp(u_i) broadcast via smem; GEMV acc_j = sum_i p_i*E_ij
// with packed f32x2 FMAs; u'_j = em_j + log(acc_j) - K, C += K, where K is
// thread 0's u from the previous step (delayed renormalizer, read after the
// one barrier per step).
// ---------------------------------------------------------------------------
__global__ void __launch_bounds__(384,1) crf_forward(
    const float* __restrict__ em, const int* __restrict__ mask,
    const float* __restrict__ startt, const float* __restrict__ endt,
    const float* __restrict__ trans)
{
  __shared__ float pbuf[ENG][2][TT];
  __shared__ float kbuf[ENG][2];
  __shared__ float red[ENG][8];

  const int tid  = threadIdx.x;
  const int eng  = tid >> 7;      // 0..2
  const int j    = tid & 127;     // state index owned by this thread
  const int lane = tid & 31;
  const int wrp  = (tid & 127) >> 5;
  const int barid = eng + 1;      // named barrier per engine

  // Load E column into registers, packed as f32x2 pairs (i, i+1).
  // Loads are coalesced across threads (consecutive j for fixed i).
  unsigned long long E2[64];
  #pragma unroll
  for (int q = 0; q < 64; ++q){
    float e0 = fex2(trans[(2*q  )*TT + j] * L2E);
    float e1 = fex2(trans[(2*q+1)*TT + j] * L2E);
    unsigned long long pk;
    asm("mov.b64 %0,{%1,%2};":"=l"(pk):"f"(e0),"f"(e1));
    E2[q] = pk;
  }
  const float endj = endt[j];
  const float stj  = startt[j];

  const uint32_t pb0 = (uint32_t)__cvta_generic_to_shared(&pbuf[eng][0][0]);

  const int ge = eng*GRID_F + blockIdx.x;   // global engine id (0..443)

  for (int b = ge; b < BB; b += NENG){
    asm volatile("bar.sync %0,128;"::"r"(barid):"memory");

    const float* eb = em + (long long)b*SS*TT + j;
    const int*   mb = mask + b*SS;

    float u = stj + eb[0];      // scores(0) = start + em[:,0,:]
    float C = 0.f;
    if (j == 0) kbuf[eng][0] = u;   // initial renormalizer

    // 2-deep emission/mask prefetch
    float emA = eb[TT];
    float emB = eb[2*TT];
    int   mkA = mb[1];
    int   mkB = mb[2];

    #pragma unroll 2
    for (int s = 1; s < SS; ++s){
      // ---- phase A: publish p_j = exp(u_j) ----
      float p = fex2(u * L2E);
      pbuf[eng][s&1][j] = p;

      // prefetch step s+2 inputs (hide DRAM latency ~2 step-times)
      float emN = 0.f; int mkN = 0;
      if (s + 2 < SS){ emN = eb[(s+2)*TT]; mkN = mb[s+2]; }

      asm volatile("bar.sync %0,128;"::"r"(barid):"memory");

      // ---- phase B: GEMV acc_j = sum_i p_i * E_ij (f32x2, 4 acc chains) ----
      unsigned long long a0=0ull, a1=0ull, a2=0ull, a3=0ull;
      const uint32_t pb = pb0 + (uint32_t)((s&1)*(TT*4));
      #pragma unroll
      for (int q = 0; q < 32; ++q){
        unsigned long long p01, p23;
        asm volatile("ld.shared.v2.b64 {%0,%1},[%2];"
                     :"=l"(p01),"=l"(p23):"r"(pb + q*16));
        if (q & 1){ FMA2(a2, E2[2*q], p01, a2); FMA2(a3, E2[2*q+1], p23, a3); }
        else      { FMA2(a0, E2[2*q], p01, a0); FMA2(a1, E2[2*q+1], p23, a1); }
      }
      float K = kbuf[eng][(s-1)&1];   // renormalizer from previous step
      ADD2(a0,a0,a2); ADD2(a1,a1,a3); ADD2(a0,a0,a1);
      float lo, hi;
      asm("mov.b64 {%0,%1},%2;":"=f"(lo),"=f"(hi):"l"(a0));
      float acc = lo + hi;

      float v = fmaf(flg2(acc), LN2, emA);   // em_j + log(acc_j)
      if (mkA > 0){ u = v - K; C += K; }     // masked update
      if (j == 0) kbuf[eng][s&1] = u;        // publish next renormalizer

      emA = emB; emB = emN; mkA = mkB; mkB = mkN;
    }

    // ---- final: denom_b = C + logsumexp_j(u_j + end_j) (exact max here) ----
    float w = u + endj;
    float m = w;
    #pragma unroll
    for (int o = 16; o; o >>= 1) m = fmaxf(m, __shfl_xor_sync(0xffffffffu, m, o));
    if (lane == 0) red[eng][wrp] = m;
    asm volatile("bar.sync %0,128;"::"r"(barid):"memory");
    m = fmaxf(fmaxf(red[eng][0], red[eng][1]), fmaxf(red[eng][2], red[eng][3]));
    float e = fex2((w - m) * L2E);
    #pragma unroll
    for (int o = 16; o; o >>= 1) e += __shfl_xor_sync(0xffffffffu, e, o);
    if (lane == 0) red[eng][4 + wrp] = e;
    asm volatile("bar.sync %0,128;"::"r"(barid):"memory");
    if (j == 0){
      float ssum = red[eng][4] + red[eng][5] + red[eng][6] + red[eng][7];
      g_denom[b] = C + m + flg2(ssum) * LN2;
    }
  }
}

// ---------------------------------------------------------------------------
// Numerator path score: one warp per batch (gathers, trivial cost).
// ---------------------------------------------------------------------------
__global__ void __launch_bounds__(1024) crf_num(
    const float* __restrict__ em, const int* __restrict__ tags,
    const int* __restrict__ mask, const float* __restrict__ startt,
    const float* __restrict__ endt, const float* __restrict__ trans)
{
  int gw   = (blockIdx.x*blockDim.x + threadIdx.x) >> 5;
  int lane = threadIdx.x & 31;
  if (gw >= BB) return;
  const int*   tg = tags + gw*SS;
  const int*   mk = mask + gw*SS;
  const float* eb = em + (long long)gw*SS*TT;

  float acc = 0.f;
  int cnt = 0;
  for (int s = lane; s < SS; s += 32){
    int m = mk[s];
    cnt += (m > 0);
    if (s > 0 && m > 0){
      int tp = tg[s-1], tc = tg[s];
      acc += trans[tp*TT + tc] + eb[s*TT + tc];
    }
  }
  #pragma unroll
  for (int o = 16; o; o >>= 1){
    acc += __shfl_xor_sync(0xffffffffu, acc, o);
    cnt += __shfl_xor_sync(0xffffffffu, cnt, o);
  }
  if (lane == 0){
    int t0 = tg[0];
    g_num[gw] = startt[t0] + eb[t0] + acc + endt[tg[cnt-1]];
  }
}

// ---------------------------------------------------------------------------
// Deterministic final reduction: sum_b (num_b - denom_b)
// ---------------------------------------------------------------------------
__global__ void crf_final(float* out)
{
  __shared__ float sm[256];
  int t = threadIdx.x;
  float a = 0.f;
  for (int b = t; b < BB; b += 256) a += g_num[b] - g_denom[b];
  sm[t] = a; __syncthreads();
  #pragma unroll
  for (int o = 128; o; o >>= 1){
    if (t < o) sm[t] += sm[t + o];
    __syncthreads();
  }
  if (t == 0) out[0] = sm[0];
}

extern "C" void kernel_launch(void* const* d_in, const int* in_sizes, int n_in,
                              void* d_out, int out_size)
{
  const float* em    = (const float*)d_in[0];
  const int*   tags  = (const int*)  d_in[1];
  const int*   mask  = (const int*)  d_in[2];
  const float* st    = (const float*)d_in[3];
  const float* en    = (const float*)d_in[4];
  const float* tr    = (const float*)d_in[5];
  float* out = (float*)d_out;

  crf_num<<<16, 1024>>>(em, tags, mask, st, en, tr);
  crf_forward<<<GRID_F, 384>>>(em, mask, st, en, tr);
  crf_final<<<1, 256>>>(out);
}